// round 1
// baseline (speedup 1.0000x reference)
#include <cuda_runtime.h>
#include <math.h>

// Problem constants
#define Bn 16
#define Cn 64
#define Hn 256
#define Wn 256
#define HW (Hn * Wn)            // 65536
#define HW4 (HW / 4)            // 16384 (float4 granularity)

// Scratch (device globals; allocation is forbidden)
__device__ float4 g_avg[Bn * HW4];   // 4 MB
__device__ float4 g_max[Bn * HW4];   // 4 MB
__device__ float4 g_att[Bn * HW4];   // 4 MB

// ---------------------------------------------------------------------------
// Kernel 1: channel mean + max.  One thread per 4 pixels (float4 along W).
// Reads 268 MB, writes 8.4 MB. Fully coalesced; DRAM-bound.
// ---------------------------------------------------------------------------
__global__ void __launch_bounds__(256) reduce_k(const float4* __restrict__ x) {
    int idx = blockIdx.x * blockDim.x + threadIdx.x;   // 0 .. Bn*HW4-1
    if (idx >= Bn * HW4) return;
    int b = idx >> 14;              // / HW4
    int p = idx & (HW4 - 1);

    const float4* xp = x + (size_t)b * Cn * HW4 + p;

    float4 v = xp[0];
    float sx = v.x, sy = v.y, sz = v.z, sw = v.w;
    float mx = v.x, my = v.y, mz = v.z, mw = v.w;

#pragma unroll 8
    for (int c = 1; c < Cn; c++) {
        v = xp[(size_t)c * HW4];
        sx += v.x; sy += v.y; sz += v.z; sw += v.w;
        mx = fmaxf(mx, v.x); my = fmaxf(my, v.y);
        mz = fmaxf(mz, v.z); mw = fmaxf(mw, v.w);
    }

    const float inv = 1.0f / (float)Cn;
    g_avg[idx] = make_float4(sx * inv, sy * inv, sz * inv, sw * inv);
    g_max[idx] = make_float4(mx, my, mz, mw);
}

// ---------------------------------------------------------------------------
// Kernel 2: 7x7 conv over [avg, max] (2 in-ch, 1 out-ch), bias, sigmoid.
// Tile 32x8 outputs per 256-thread block, smem halo of 38x14 per channel.
// Tiny kernel (~1M output pixels); LDS-bound, a few microseconds.
// ---------------------------------------------------------------------------
#define TX 32
#define TY 8
#define HALO 3
#define SW_ (TX + 2 * HALO)      // 38
#define SH_ (TY + 2 * HALO)      // 14
#define SPITCH 40                // pad to dodge bank conflicts

__global__ void __launch_bounds__(256) conv_k(const float* __restrict__ wgt,
                                              const float* __restrict__ bias) {
    __shared__ float sa[SH_ * SPITCH];
    __shared__ float sm[SH_ * SPITCH];
    __shared__ float swt[99];    // 98 weights + bias

    const int tid = threadIdx.x;                  // 0..255
    const int tx  = tid & 31;
    const int ty  = tid >> 5;
    const int bx  = blockIdx.x;                   // 0..7   (W tiles)
    const int by  = blockIdx.y;                   // 0..31  (H tiles)
    const int b   = blockIdx.z;                   // 0..15

    if (tid < 98) swt[tid] = wgt[tid];
    if (tid == 98) swt[98] = bias[0];

    const float* avgp = (const float*)g_avg + (size_t)b * HW;
    const float* maxp = (const float*)g_max + (size_t)b * HW;

    const int h0 = by * TY - HALO;
    const int w0 = bx * TX - HALO;

    // cooperative halo load with zero padding
    for (int i = tid; i < SH_ * SW_; i += 256) {
        int r = i / SW_;
        int c = i - r * SW_;
        int h = h0 + r;
        int w = w0 + c;
        float a = 0.0f, m = 0.0f;
        if ((unsigned)h < Hn && (unsigned)w < Wn) {
            int off = h * Wn + w;
            a = avgp[off];
            m = maxp[off];
        }
        sa[r * SPITCH + c] = a;
        sm[r * SPITCH + c] = m;
    }
    __syncthreads();

    float acc = swt[98];
#pragma unroll
    for (int ky = 0; ky < 7; ky++) {
#pragma unroll
        for (int kx = 0; kx < 7; kx++) {
            int si = (ty + ky) * SPITCH + (tx + kx);
            acc = fmaf(sa[si], swt[ky * 7 + kx], acc);
            acc = fmaf(sm[si], swt[49 + ky * 7 + kx], acc);
        }
    }

    float att = 1.0f / (1.0f + expf(-acc));

    int oh = by * TY + ty;
    int ow = bx * TX + tx;
    ((float*)g_att)[(size_t)b * HW + oh * Wn + ow] = att;
}

// ---------------------------------------------------------------------------
// Kernel 3: out = x * att (att broadcast over channels).
// Reads 268 MB x + 4 MB att (L2-resident after first touch), writes 268 MB.
// ---------------------------------------------------------------------------
__global__ void __launch_bounds__(256) mul_k(const float4* __restrict__ x,
                                             float4* __restrict__ out) {
    int idx = blockIdx.x * blockDim.x + threadIdx.x;  // 0 .. Bn*Cn*HW4-1
    if (idx >= Bn * Cn * HW4) return;
    int b = idx >> 20;              // / (Cn*HW4)
    int p = idx & (HW4 - 1);

    float4 a = g_att[(b << 14) + p];
    float4 v = x[idx];
    v.x *= a.x; v.y *= a.y; v.z *= a.z; v.w *= a.w;
    out[idx] = v;
}

// ---------------------------------------------------------------------------
extern "C" void kernel_launch(void* const* d_in, const int* in_sizes, int n_in,
                              void* d_out, int out_size) {
    const float4* x    = (const float4*)d_in[0];
    const float*  wgt  = (const float*)d_in[1];
    const float*  bias = (const float*)d_in[2];
    float4*       out  = (float4*)d_out;

    {
        int total = Bn * HW4;                  // 262144
        reduce_k<<<(total + 255) / 256, 256>>>(x);
    }
    {
        dim3 grid(Wn / TX, Hn / TY, Bn);       // (8, 32, 16)
        conv_k<<<grid, 256>>>(wgt, bias);
    }
    {
        int total = Bn * Cn * HW4;             // 16777216
        mul_k<<<(total + 255) / 256, 256>>>(x, out);
    }
}

// round 2
// speedup vs baseline: 1.0251x; 1.0251x over previous
#include <cuda_runtime.h>
#include <math.h>

// Problem constants
#define Bn 16
#define Cn 64
#define Hn 256
#define Wn 256
#define HW (Hn * Wn)            // 65536
#define HW4 (HW / 4)            // 16384 (float4 granularity)

// Scratch (device globals; allocation is forbidden)
__device__ float4 g_avg[Bn * HW4];   // 4 MB
__device__ float4 g_max[Bn * HW4];   // 4 MB
__device__ float4 g_att[Bn * HW4];   // 4 MB

// ---------------------------------------------------------------------------
// Kernel 1: channel mean + max.  One thread per 4 pixels (float4 along W).
// Reads 268 MB (streaming, evict-first), writes 8.4 MB (keep in L2 for conv).
// ---------------------------------------------------------------------------
__global__ void __launch_bounds__(256) reduce_k(const float4* __restrict__ x) {
    int idx = blockIdx.x * blockDim.x + threadIdx.x;   // 0 .. Bn*HW4-1
    if (idx >= Bn * HW4) return;
    int b = idx >> 14;              // / HW4
    int p = idx & (HW4 - 1);

    const float4* xp = x + (size_t)b * Cn * HW4 + p;

    float4 v = __ldcs(xp);
    float sx = v.x, sy = v.y, sz = v.z, sw = v.w;
    float mx = v.x, my = v.y, mz = v.z, mw = v.w;

#pragma unroll 8
    for (int c = 1; c < Cn; c++) {
        v = __ldcs(xp + (size_t)c * HW4);
        sx += v.x; sy += v.y; sz += v.z; sw += v.w;
        mx = fmaxf(mx, v.x); my = fmaxf(my, v.y);
        mz = fmaxf(mz, v.z); mw = fmaxf(mw, v.w);
    }

    const float inv = 1.0f / (float)Cn;
    g_avg[idx] = make_float4(sx * inv, sy * inv, sz * inv, sw * inv);
    g_max[idx] = make_float4(mx, my, mz, mw);
}

// ---------------------------------------------------------------------------
// Kernel 2: 7x7 conv over [avg, max] (2 in-ch, 1 out-ch), bias, sigmoid.
// Tile 32x8 outputs per 256-thread block, smem halo 38x14 per channel.
// ---------------------------------------------------------------------------
#define TX 32
#define TY 8
#define HALO 3
#define SW_ (TX + 2 * HALO)      // 38
#define SH_ (TY + 2 * HALO)      // 14
#define SPITCH 40                // pad to dodge bank conflicts

__global__ void __launch_bounds__(256) conv_k(const float* __restrict__ wgt,
                                              const float* __restrict__ bias) {
    __shared__ float sa[SH_ * SPITCH];
    __shared__ float sm[SH_ * SPITCH];
    __shared__ float swt[99];    // 98 weights + bias

    const int tid = threadIdx.x;                  // 0..255
    const int tx  = tid & 31;
    const int ty  = tid >> 5;
    const int bx  = blockIdx.x;                   // 0..7   (W tiles)
    const int by  = blockIdx.y;                   // 0..31  (H tiles)
    const int b   = blockIdx.z;                   // 0..15

    if (tid < 98) swt[tid] = wgt[tid];
    if (tid == 98) swt[98] = bias[0];

    const float* avgp = (const float*)g_avg + (size_t)b * HW;
    const float* maxp = (const float*)g_max + (size_t)b * HW;

    const int h0 = by * TY - HALO;
    const int w0 = bx * TX - HALO;

    // cooperative halo load with zero padding
    for (int i = tid; i < SH_ * SW_; i += 256) {
        int r = i / SW_;
        int c = i - r * SW_;
        int h = h0 + r;
        int w = w0 + c;
        float a = 0.0f, m = 0.0f;
        if ((unsigned)h < Hn && (unsigned)w < Wn) {
            int off = h * Wn + w;
            a = avgp[off];
            m = maxp[off];
        }
        sa[r * SPITCH + c] = a;
        sm[r * SPITCH + c] = m;
    }
    __syncthreads();

    float acc = swt[98];
#pragma unroll
    for (int ky = 0; ky < 7; ky++) {
#pragma unroll
        for (int kx = 0; kx < 7; kx++) {
            int si = (ty + ky) * SPITCH + (tx + kx);
            acc = fmaf(sa[si], swt[ky * 7 + kx], acc);
            acc = fmaf(sm[si], swt[49 + ky * 7 + kx], acc);
        }
    }

    float att = 1.0f / (1.0f + expf(-acc));

    int oh = by * TY + ty;
    int ow = bx * TX + tx;
    ((float*)g_att)[(size_t)b * HW + oh * Wn + ow] = att;
}

// ---------------------------------------------------------------------------
// Kernel 3: out = x * att (att broadcast over channels).
// Each thread: 1 att float4 + 4 channels' x float4 (batched loads -> MLP=4),
// streaming load (__ldcs) and streaming store (__stcs). att stays in L2.
// ---------------------------------------------------------------------------
__global__ void __launch_bounds__(256) mul_k(const float4* __restrict__ x,
                                             float4* __restrict__ out) {
    int idx = blockIdx.x * blockDim.x + threadIdx.x;  // 0 .. Bn*16*HW4-1
    if (idx >= Bn * (Cn / 4) * HW4) return;

    int p  = idx & (HW4 - 1);
    int t  = idx >> 14;         // b*16 + cg
    int b  = t >> 4;
    int cg = t & 15;            // channel group (4 channels each)

    size_t xoff = ((size_t)b * Cn + (size_t)cg * 4) * HW4 + p;
    const float4* xp = x + xoff;
    float4*       op = out + xoff;

    float4 a = g_att[(b << 14) + p];

    // batch the 4 loads up front for memory-level parallelism
    float4 v0 = __ldcs(xp);
    float4 v1 = __ldcs(xp + HW4);
    float4 v2 = __ldcs(xp + 2 * HW4);
    float4 v3 = __ldcs(xp + 3 * HW4);

    v0.x *= a.x; v0.y *= a.y; v0.z *= a.z; v0.w *= a.w;
    v1.x *= a.x; v1.y *= a.y; v1.z *= a.z; v1.w *= a.w;
    v2.x *= a.x; v2.y *= a.y; v2.z *= a.z; v2.w *= a.w;
    v3.x *= a.x; v3.y *= a.y; v3.z *= a.z; v3.w *= a.w;

    __stcs(op,           v0);
    __stcs(op + HW4,     v1);
    __stcs(op + 2 * HW4, v2);
    __stcs(op + 3 * HW4, v3);
}

// ---------------------------------------------------------------------------
extern "C" void kernel_launch(void* const* d_in, const int* in_sizes, int n_in,
                              void* d_out, int out_size) {
    const float4* x    = (const float4*)d_in[0];
    const float*  wgt  = (const float*)d_in[1];
    const float*  bias = (const float*)d_in[2];
    float4*       out  = (float4*)d_out;

    {
        int total = Bn * HW4;                  // 262144
        reduce_k<<<(total + 255) / 256, 256>>>(x);
    }
    {
        dim3 grid(Wn / TX, Hn / TY, Bn);       // (8, 32, 16)
        conv_k<<<grid, 256>>>(wgt, bias);
    }
    {
        int total = Bn * (Cn / 4) * HW4;       // 4194304
        mul_k<<<(total + 255) / 256, 256>>>(x, out);
    }
}